// round 9
// baseline (speedup 1.0000x reference)
#include <cuda_runtime.h>
#include <cuda_bf16.h>

#define THREADS   256
#define ITEMS     8
#define BLOCK_NNZ (32 * ITEMS)   // nnz per warp-block = 256
#define NUM_CTAS  (148 * 6)      // one full wave at occupancy 6
#define FULLMASK  0xffffffffu

__global__ void init_out_kernel(float* __restrict__ y,
                                const float* __restrict__ bias, int n) {
    int i  = blockIdx.x * blockDim.x + threadIdx.x;
    int i4 = i * 4;
    if (i4 + 4 <= n) {
        float4 b = *reinterpret_cast<const float4*>(bias + i4);
        *reinterpret_cast<float4*>(y + i4) = b;
    } else if (i4 < n) {
        for (int k = i4; k < n; k++) y[k] = bias[k];
    }
}

__device__ __forceinline__
void process_full_block(const float* __restrict__ vals,
                        const float* __restrict__ x,
                        const int*   __restrict__ rows,
                        const int*   __restrict__ cols,
                        float*       __restrict__ y,
                        unsigned base, int lane) {
    // ---- Streaming loads: evict-first so x keeps L1 residency ----
    const int4*   rp = reinterpret_cast<const int4*>(rows + base);
    const int4*   cp = reinterpret_cast<const int4*>(cols + base);
    const float4* vp = reinterpret_cast<const float4*>(vals + base);

    int4   c0 = __ldcs(&cp[0]);
    int4   c1 = __ldcs(&cp[1]);
    int4   r0 = __ldcs(&rp[0]);
    int4   r1 = __ldcs(&rp[1]);
    float4 v0 = __ldcs(&vp[0]);
    float4 v1 = __ldcs(&vp[1]);

    // ---- Gather x: 8 independent random 4B loads ----
    float xv[ITEMS];
    xv[0] = __ldg(&x[c0.x]);
    xv[1] = __ldg(&x[c0.y]);
    xv[2] = __ldg(&x[c0.z]);
    xv[3] = __ldg(&x[c0.w]);
    xv[4] = __ldg(&x[c1.x]);
    xv[5] = __ldg(&x[c1.y]);
    xv[6] = __ldg(&x[c1.z]);
    xv[7] = __ldg(&x[c1.w]);

    int   r[ITEMS] = {r0.x, r0.y, r0.z, r0.w, r1.x, r1.y, r1.z, r1.w};
    float v[ITEMS] = {v0.x, v0.y, v0.z, v0.w, v1.x, v1.y, v1.z, v1.w};

    // ---- Per-thread segment scan; direct atomic on each boundary ----
    float acc = 0.0f;
    int   cur = r[0];
    #pragma unroll
    for (int i = 0; i < ITEMS; i++) {
        if (r[i] != cur) {
            atomicAdd(&y[cur], acc);
            acc = 0.0f;
            cur = r[i];
        }
        acc = fmaf(v[i], xv[i], acc);
    }

    // ---- Warp segmented inclusive scan over tail accumulators.
    //      Rows sorted => equal tail rows are lane-contiguous. ----
    int lrprev = __shfl_up_sync(FULLMASK, cur, 1);
    unsigned headf = (lane == 0) || (cur != lrprev);

    float    vsum = acc;
    unsigned stop = headf;
    #pragma unroll
    for (int d = 1; d < 32; d <<= 1) {
        float    pv = __shfl_up_sync(FULLMASK, vsum, d);
        unsigned ps = __shfl_up_sync(FULLMASK, stop, d);
        if (lane >= d && !stop) { vsum += pv; stop = ps; }
    }
    unsigned hnext = __shfl_down_sync(FULLMASK, headf, 1);
    if (lane == 31 || hnext) atomicAdd(&y[cur], vsum);
}

__global__ __launch_bounds__(THREADS)
void spmv_coo_kernel(const float* __restrict__ vals,
                     const float* __restrict__ x,
                     const int*   __restrict__ rows,
                     const int*   __restrict__ cols,
                     float*       __restrict__ y,
                     unsigned nnz) {
    const int      lane   = threadIdx.x & 31;
    const unsigned warpId = (blockIdx.x * THREADS + threadIdx.x) >> 5;
    const unsigned nWarps = gridDim.x * (THREADS / 32);
    const unsigned nFull  = nnz / BLOCK_NNZ;   // fully in-range warp-blocks

    // Persistent grid-stride over full blocks: collective path only.
    for (unsigned b = warpId; b < nFull; b += nWarps) {
        process_full_block(vals, x, rows, cols, y, b * BLOCK_NNZ + lane * ITEMS, lane);
    }

    // Epilogue: remaining nnz handled by warp 0, scalar per lane.
    if (warpId == 0) {
        unsigned tailBase = nFull * BLOCK_NNZ;
        unsigned base = tailBase + (unsigned)lane * ITEMS;
        if (base < nnz) {
            unsigned end = base + ITEMS;
            if (end > nnz) end = nnz;
            float acc = 0.0f;
            int   cur = rows[base];
            for (unsigned i = base; i < end; i++) {
                int   ri = rows[i];
                int   ci = cols[i];
                float vi = vals[i];
                if (ri != cur) {
                    atomicAdd(&y[cur], acc);
                    acc = 0.0f;
                    cur = ri;
                }
                acc = fmaf(vi, __ldg(&x[ci]), acc);
            }
            atomicAdd(&y[cur], acc);
        }
    }
}

extern "C" void kernel_launch(void* const* d_in, const int* in_sizes, int n_in,
                              void* d_out, int out_size) {
    // metadata order: vals[NNZ] f32, x[N_COLS] f32, bias[N_ROWS] f32,
    //                 rows[NNZ] i32, cols[NNZ] i32, n_rows (ignored)
    const float* vals = (const float*)d_in[0];
    const float* x    = (const float*)d_in[1];
    const float* bias = (const float*)d_in[2];
    const int*   rows = (const int*)d_in[3];
    const int*   cols = (const int*)d_in[4];
    float* y = (float*)d_out;

    unsigned nnz = (unsigned)in_sizes[0];
    int n_rows   = in_sizes[2];

    // 1) y = bias  (vectorized; d_out is poisoned before timing)
    {
        int quads = (n_rows + 3) / 4;
        int grid  = (quads + THREADS - 1) / THREADS;
        init_out_kernel<<<grid, THREADS>>>(y, bias, n_rows);
    }

    // 2) y += segment_sum(vals * x[cols]) — persistent grid-stride, one wave
    {
        unsigned nBlocks    = (nnz + BLOCK_NNZ - 1) / BLOCK_NNZ;
        unsigned ctasNeeded = (nBlocks + (THREADS / 32) - 1) / (THREADS / 32);
        unsigned grid = ctasNeeded < (unsigned)NUM_CTAS ? ctasNeeded : (unsigned)NUM_CTAS;
        if (grid == 0) grid = 1;
        spmv_coo_kernel<<<grid, THREADS>>>(vals, x, rows, cols, y, nnz);
    }
}